// round 1
// baseline (speedup 1.0000x reference)
#include <cuda_runtime.h>
#include <math.h>

#define BB 16
#define SEQ 512
#define DIM 512
#define NH 8
#define HD 64
#define LWIN 64
#define NQV 10000

// ---------------- scratch (device globals; no allocation allowed) ----------------
__device__ float g_M[BB*SEQ*DIM];
__device__ float g_E[BB*SEQ*DIM];
__device__ float g_qkv[BB*SEQ*3*DIM];
__device__ float g_scores[BB*NH*SEQ*SEQ];      // 134 MB
__device__ float g_ao[BB*SEQ*DIM];
__device__ float g_proj[BB*SEQ*DIM];
__device__ float g_Sbase[BB*SEQ*DIM];
__device__ float g_Slocal[BB*SEQ*DIM];
__device__ float g_Sglobal[BB*SEQ*DIM];
__device__ float g_Scross[BB*SEQ*DIM];
__device__ float g_qkv_loc[BB*LWIN*3*DIM];
__device__ float g_sc_loc[BB*NH*LWIN*LWIN];
__device__ float g_ao_loc[BB*LWIN*DIM];
__device__ float g_S[BB*SEQ*DIM];
__device__ float g_h1[BB*SEQ*DIM];
__device__ float g_F[BB*SEQ*DIM];

// ---------------- generic batched GEMM: C = scale*(A @ B[^T]) + bias ----------------
// two-level batch: z -> (zb = z/hinner, zh = z%hinner); offsets zb*sXb + zh*sXh
#define TBM 64
#define TBN 64
#define TBK 16

__global__ __launch_bounds__(256) void gemm_k(
    const float* __restrict__ A, const float* __restrict__ B,
    const float* __restrict__ bias, float* __restrict__ C,
    int M, int N, int K, int lda, int ldb, int ldc,
    long sAb, long sAh, long sBb, long sBh, long sCb, long sCh,
    int hinner, float scale, int transB, int doRelu)
{
    __shared__ float As[TBK][TBM];
    __shared__ float Bs[TBK][TBN];

    int z  = blockIdx.z;
    int zb = z / hinner, zh = z % hinner;
    A += zb * sAb + zh * sAh;
    B += zb * sBb + zh * sBh;
    C += zb * sCb + zh * sCh;

    int m0 = blockIdx.y * TBM, n0 = blockIdx.x * TBN;
    int tid = threadIdx.x;
    int tm = tid >> 4, tn = tid & 15;

    float acc[4][4];
#pragma unroll
    for (int i = 0; i < 4; i++)
#pragma unroll
        for (int j = 0; j < 4; j++) acc[i][j] = 0.f;

    for (int k0 = 0; k0 < K; k0 += TBK) {
        // A tile: TBM x TBK
        for (int i = tid; i < TBM * TBK; i += 256) {
            int m = i / TBK, k = i % TBK;
            int gm = m0 + m, gk = k0 + k;
            As[k][m] = (gm < M && gk < K) ? A[(long)gm * lda + gk] : 0.f;
        }
        // B tile
        if (transB) {
            for (int i = tid; i < TBN * TBK; i += 256) {
                int n = i / TBK, k = i % TBK;
                int gn = n0 + n, gk = k0 + k;
                Bs[k][n] = (gn < N && gk < K) ? B[(long)gn * ldb + gk] : 0.f;
            }
        } else {
            for (int i = tid; i < TBK * TBN; i += 256) {
                int k = i / TBN, n = i % TBN;
                int gk = k0 + k, gn = n0 + n;
                Bs[k][n] = (gk < K && gn < N) ? B[(long)gk * ldb + gn] : 0.f;
            }
        }
        __syncthreads();
#pragma unroll
        for (int k = 0; k < TBK; k++) {
            float4 a4 = *reinterpret_cast<const float4*>(&As[k][tm * 4]);
            float4 b4 = *reinterpret_cast<const float4*>(&Bs[k][tn * 4]);
            float a[4] = {a4.x, a4.y, a4.z, a4.w};
            float b[4] = {b4.x, b4.y, b4.z, b4.w};
#pragma unroll
            for (int i = 0; i < 4; i++)
#pragma unroll
                for (int j = 0; j < 4; j++) acc[i][j] += a[i] * b[j];
        }
        __syncthreads();
    }

#pragma unroll
    for (int i = 0; i < 4; i++) {
        int gm = m0 + tm * 4 + i;
        if (gm >= M) continue;
#pragma unroll
        for (int j = 0; j < 4; j++) {
            int gn = n0 + tn * 4 + j;
            if (gn >= N) continue;
            float v = acc[i][j] * scale;
            if (bias) v += bias[gn];
            if (doRelu) v = fmaxf(v, 0.f);
            C[(long)gm * ldc + gn] = v;
        }
    }
}

// ---------------- embedding gather ----------------
__global__ void embed_k(const int* __restrict__ q, const int* __restrict__ r,
                        const int* __restrict__ qry,
                        const float* __restrict__ Memb, const float* __restrict__ Eemb,
                        const float* __restrict__ P)
{
    long idx = (long)blockIdx.x * blockDim.x + threadIdx.x;
    long total = (long)BB * SEQ * DIM;
    if (idx >= total) return;
    int d = (int)(idx % DIM);
    long bn = idx / DIM;
    int n = (int)(bn % SEQ);
    int x = q[bn] + NQV * r[bn];
    g_M[idx] = Memb[(long)x * DIM + d] + P[n * DIM + d];
    g_E[idx] = Eemb[(long)qry[bn] * DIM + d];
}

// ---------------- block reductions ----------------
__device__ __forceinline__ float blk_reduce(float v, bool is_max, float ident) {
    __shared__ float red[32];
    __shared__ float bc;
    int t = threadIdx.x;
    int nw = blockDim.x >> 5;
#pragma unroll
    for (int o = 16; o; o >>= 1) {
        float other = __shfl_xor_sync(0xffffffffu, v, o);
        v = is_max ? fmaxf(v, other) : (v + other);
    }
    if ((t & 31) == 0) red[t >> 5] = v;
    __syncthreads();
    if (t < 32) {
        float s = (t < nw) ? red[t] : ident;
#pragma unroll
        for (int o = 16; o; o >>= 1) {
            float other = __shfl_xor_sync(0xffffffffu, s, o);
            s = is_max ? fmaxf(s, other) : (s + other);
        }
        if (t == 0) bc = s;
    }
    __syncthreads();
    float ret = bc;
    __syncthreads();
    return ret;
}

// ---------------- softmax over rows (causal => only first i+1 cols valid, tail zeroed) ----------------
__global__ void softmax_k(float* __restrict__ S, int rows_per, int cols, int causal)
{
    long row = blockIdx.x;
    int i = (int)(row % rows_per);
    float* p = S + row * (long)cols;
    int lim = causal ? (i + 1) : cols;
    int t = threadIdx.x;

    float mx = -1e30f;
    for (int j = t; j < lim; j += blockDim.x) mx = fmaxf(mx, p[j]);
    float gmax = blk_reduce(mx, true, -1e30f);

    float s = 0.f;
    for (int j = t; j < lim; j += blockDim.x) { float e = expf(p[j] - gmax); p[j] = e; s += e; }
    float gsum = blk_reduce(s, false, 0.f);

    float inv = 1.f / gsum;
    for (int j = t; j < lim; j += blockDim.x) p[j] *= inv;
    for (int j = lim + t; j < cols; j += blockDim.x) p[j] = 0.f;
}

// ---------------- head-mean of base attention into output ----------------
__global__ void attn_mean_k(const float* __restrict__ S, float* __restrict__ out)
{
    long idx = (long)blockIdx.x * blockDim.x + threadIdx.x;
    long total = (long)BB * SEQ * SEQ;
    if (idx >= total) return;
    long b = idx / ((long)SEQ * SEQ);
    long rem = idx % ((long)SEQ * SEQ);
    float s = 0.f;
#pragma unroll
    for (int h = 0; h < NH; h++)
        s += S[((long)(b * NH + h)) * SEQ * SEQ + rem];
    out[idx] = s * (1.f / NH);
}

// ---------------- fused residual add + LayerNorm (c may be null) ----------------
__global__ __launch_bounds__(256) void add_ln_k(
    const float* __restrict__ a, const float* __restrict__ b, const float* __restrict__ c,
    const float* __restrict__ gam, const float* __restrict__ bet, float* __restrict__ out)
{
    long row = blockIdx.x;
    int t = threadIdx.x;
    long base = row * (long)DIM;
    float x0 = a[base + t] + b[base + t] + (c ? c[base + t] : 0.f);
    float x1 = a[base + t + 256] + b[base + t + 256] + (c ? c[base + t + 256] : 0.f);
    float mean = blk_reduce(x0 + x1, false, 0.f) * (1.f / DIM);
    float d0 = x0 - mean, d1 = x1 - mean;
    float var = blk_reduce(d0 * d0 + d1 * d1, false, 0.f) * (1.f / DIM);
    float inv = rsqrtf(var + 1e-5f);
    out[base + t]       = d0 * inv * gam[t]       + bet[t];
    out[base + t + 256] = d1 * inv * gam[t + 256] + bet[t + 256];
}

// ---------------- misc elementwise ----------------
__global__ void zero_k(float* __restrict__ p, long n)
{
    long idx = (long)blockIdx.x * blockDim.x + threadIdx.x;
    if (idx < n) p[idx] = 0.f;
}

__global__ void sum4_k(const float* __restrict__ a, const float* __restrict__ b,
                       const float* __restrict__ c, const float* __restrict__ d,
                       float* __restrict__ out, long n)
{
    long idx = (long)blockIdx.x * blockDim.x + threadIdx.x;
    if (idx < n) out[idx] = a[idx] + b[idx] + c[idx] + d[idx];
}

// ---------------- prediction head: sigmoid(F @ w^T + b) ----------------
__global__ void pred_k(const float* __restrict__ F, const float* __restrict__ w,
                       const float* __restrict__ bias, float* __restrict__ out)
{
    int gw = (blockIdx.x * blockDim.x + threadIdx.x) >> 5;
    int lane = threadIdx.x & 31;
    if (gw >= BB * SEQ) return;
    const float* f = F + (long)gw * DIM;
    float s = 0.f;
    for (int j = lane; j < DIM; j += 32) s += f[j] * w[j];
#pragma unroll
    for (int o = 16; o; o >>= 1) s += __shfl_xor_sync(0xffffffffu, s, o);
    if (lane == 0) out[gw] = 1.f / (1.f + expf(-(s + bias[0])));
}

// ---------------- host side ----------------
static float* sym_addr(const void* symbol) {
    void* p = nullptr;
    cudaGetSymbolAddress(&p, symbol);
    return (float*)p;
}

static void gemm(const float* A, const float* B, const float* bias, float* C,
                 int M, int N, int K, int lda, int ldb, int ldc,
                 long sAb, long sAh, long sBb, long sBh, long sCb, long sCh,
                 int batch, int hinner, float scale, bool transB, bool relu)
{
    dim3 grid((N + TBN - 1) / TBN, (M + TBM - 1) / TBM, batch);
    gemm_k<<<grid, 256>>>(A, B, bias, C, M, N, K, lda, ldb, ldc,
                          sAb, sAh, sBb, sBh, sCb, sCh, hinner, scale,
                          transB ? 1 : 0, relu ? 1 : 0);
}

extern "C" void kernel_launch(void* const* d_in, const int* in_sizes, int n_in,
                              void* d_out, int out_size)
{
    const int*   q_i    = (const int*)d_in[0];
    const int*   r_i    = (const int*)d_in[1];
    const int*   qry_i  = (const int*)d_in[2];
    const float* Memb   = (const float*)d_in[3];
    const float* Eemb   = (const float*)d_in[4];
    const float* P      = (const float*)d_in[5];
    const float* base_iw = (const float*)d_in[6];
    const float* base_ib = (const float*)d_in[7];
    const float* base_ow = (const float*)d_in[8];
    const float* base_ob = (const float*)d_in[9];
    const float* loc_iw  = (const float*)d_in[10];
    const float* loc_ib  = (const float*)d_in[11];
    const float* loc_ow  = (const float*)d_in[12];
    const float* loc_ob  = (const float*)d_in[13];
    const float* glob_iw = (const float*)d_in[14];
    const float* glob_ib = (const float*)d_in[15];
    const float* glob_ow = (const float*)d_in[16];
    const float* glob_ob = (const float*)d_in[17];
    const float* cross_iw = (const float*)d_in[18];
    const float* cross_ib = (const float*)d_in[19];
    const float* cross_ow = (const float*)d_in[20];
    const float* cross_ob = (const float*)d_in[21];
    const float* ln1_g = (const float*)d_in[22];
    const float* ln1_b = (const float*)d_in[23];
    const float* w1 = (const float*)d_in[24];
    const float* b1 = (const float*)d_in[25];
    const float* w2 = (const float*)d_in[26];
    const float* b2 = (const float*)d_in[27];
    const float* ln2_g = (const float*)d_in[28];
    const float* ln2_b = (const float*)d_in[29];
    const float* pred_w = (const float*)d_in[30];
    const float* pred_b = (const float*)d_in[31];

    float* out   = (float*)d_out;
    float* p_out = out;                 // [B, N]
    float* a_out = out + BB * SEQ;      // [B, N, N]

    float* M_  = sym_addr(g_M);
    float* E_  = sym_addr(g_E);
    float* qkv = sym_addr(g_qkv);
    float* sc  = sym_addr(g_scores);
    float* ao  = sym_addr(g_ao);
    float* pr  = sym_addr(g_proj);
    float* Sb  = sym_addr(g_Sbase);
    float* Sl  = sym_addr(g_Slocal);
    float* Sg  = sym_addr(g_Sglobal);
    float* Sc  = sym_addr(g_Scross);
    float* qkvL = sym_addr(g_qkv_loc);
    float* scL  = sym_addr(g_sc_loc);
    float* aoL  = sym_addr(g_ao_loc);
    float* Ssum = sym_addr(g_S);
    float* h1   = sym_addr(g_h1);
    float* Ff   = sym_addr(g_F);

    const long TOT = (long)BB * SEQ * DIM;
    const int  BN3 = 3 * DIM;
    const float SCL = 0.125f;           // 1/sqrt(64)
    const int BH = BB * NH;

    // 1. embeddings
    embed_k<<<(int)((TOT + 255) / 256), 256>>>(q_i, r_i, qry_i, Memb, Eemb, P);

    // ---------- base MHA: Q from E, K/V from M, causal ----------
    gemm(E_, base_iw, base_ib, qkv, BB * SEQ, DIM, DIM, DIM, DIM, BN3,
         0, 0, 0, 0, 0, 0, 1, 1, 1.f, true, false);
    gemm(M_, base_iw + DIM * DIM, base_ib + DIM, qkv + DIM, BB * SEQ, 2 * DIM, DIM, DIM, DIM, BN3,
         0, 0, 0, 0, 0, 0, 1, 1, 1.f, true, false);
    gemm(qkv, qkv + DIM, nullptr, sc, SEQ, SEQ, HD, BN3, BN3, SEQ,
         (long)SEQ * BN3, HD, (long)SEQ * BN3, HD, (long)NH * SEQ * SEQ, (long)SEQ * SEQ,
         BH, NH, SCL, true, false);
    softmax_k<<<BH * SEQ, 128>>>(sc, SEQ, SEQ, 1);
    attn_mean_k<<<(int)(((long)BB * SEQ * SEQ + 255) / 256), 256>>>(sc, a_out);
    gemm(sc, qkv + 2 * DIM, nullptr, ao, SEQ, HD, SEQ, SEQ, BN3, DIM,
         (long)NH * SEQ * SEQ, (long)SEQ * SEQ, (long)SEQ * BN3, HD, (long)SEQ * DIM, HD,
         BH, NH, 1.f, false, false);
    gemm(ao, base_ow, base_ob, pr, BB * SEQ, DIM, DIM, DIM, DIM, DIM,
         0, 0, 0, 0, 0, 0, 1, 1, 1.f, true, false);
    add_ln_k<<<BB * SEQ, 256>>>(pr, M_, E_, ln1_g, ln1_b, Sb);

    // ---------- local MHA on last LW rows of S_base ----------
    gemm(Sb + (SEQ - LWIN) * DIM, loc_iw, loc_ib, qkvL, LWIN, BN3, DIM, DIM, DIM, BN3,
         (long)SEQ * DIM, 0, 0, 0, (long)LWIN * BN3, 0, BB, 1, 1.f, true, false);
    gemm(qkvL, qkvL + DIM, nullptr, scL, LWIN, LWIN, HD, BN3, BN3, LWIN,
         (long)LWIN * BN3, HD, (long)LWIN * BN3, HD, (long)NH * LWIN * LWIN, (long)LWIN * LWIN,
         BH, NH, SCL, true, false);
    softmax_k<<<BH * LWIN, 128>>>(scL, LWIN, LWIN, 1);
    gemm(scL, qkvL + 2 * DIM, nullptr, aoL, LWIN, HD, LWIN, LWIN, BN3, DIM,
         (long)NH * LWIN * LWIN, (long)LWIN * LWIN, (long)LWIN * BN3, HD, (long)LWIN * DIM, HD,
         BH, NH, 1.f, false, false);
    zero_k<<<(int)((TOT + 255) / 256), 256>>>(Sl, TOT);
    gemm(aoL, loc_ow, loc_ob, Sl + (SEQ - LWIN) * DIM, LWIN, DIM, DIM, DIM, DIM, DIM,
         (long)LWIN * DIM, 0, 0, 0, (long)SEQ * DIM, 0, BB, 1, 1.f, true, false);

    // ---------- global MHA: all from S_base, causal ----------
    gemm(Sb, glob_iw, glob_ib, qkv, BB * SEQ, BN3, DIM, DIM, DIM, BN3,
         0, 0, 0, 0, 0, 0, 1, 1, 1.f, true, false);
    gemm(qkv, qkv + DIM, nullptr, sc, SEQ, SEQ, HD, BN3, BN3, SEQ,
         (long)SEQ * BN3, HD, (long)SEQ * BN3, HD, (long)NH * SEQ * SEQ, (long)SEQ * SEQ,
         BH, NH, SCL, true, false);
    softmax_k<<<BH * SEQ, 128>>>(sc, SEQ, SEQ, 1);
    gemm(sc, qkv + 2 * DIM, nullptr, ao, SEQ, HD, SEQ, SEQ, BN3, DIM,
         (long)NH * SEQ * SEQ, (long)SEQ * SEQ, (long)SEQ * BN3, HD, (long)SEQ * DIM, HD,
         BH, NH, 1.f, false, false);
    gemm(ao, glob_ow, glob_ob, Sg, BB * SEQ, DIM, DIM, DIM, DIM, DIM,
         0, 0, 0, 0, 0, 0, 1, 1, 1.f, true, false);

    // ---------- cross MHA: Q from S_base, K/V from S_local, no mask ----------
    gemm(Sb, cross_iw, cross_ib, qkv, BB * SEQ, DIM, DIM, DIM, DIM, BN3,
         0, 0, 0, 0, 0, 0, 1, 1, 1.f, true, false);
    gemm(Sl, cross_iw + DIM * DIM, cross_ib + DIM, qkv + DIM, BB * SEQ, 2 * DIM, DIM, DIM, DIM, BN3,
         0, 0, 0, 0, 0, 0, 1, 1, 1.f, true, false);
    gemm(qkv, qkv + DIM, nullptr, sc, SEQ, SEQ, HD, BN3, BN3, SEQ,
         (long)SEQ * BN3, HD, (long)SEQ * BN3, HD, (long)NH * SEQ * SEQ, (long)SEQ * SEQ,
         BH, NH, SCL, true, false);
    softmax_k<<<BH * SEQ, 128>>>(sc, SEQ, SEQ, 0);
    gemm(sc, qkv + 2 * DIM, nullptr, ao, SEQ, HD, SEQ, SEQ, BN3, DIM,
         (long)NH * SEQ * SEQ, (long)SEQ * SEQ, (long)SEQ * BN3, HD, (long)SEQ * DIM, HD,
         BH, NH, 1.f, false, false);
    gemm(ao, cross_ow, cross_ob, Sc, BB * SEQ, DIM, DIM, DIM, DIM, DIM,
         0, 0, 0, 0, 0, 0, 1, 1, 1.f, true, false);

    // ---------- combine + FFN + LN + pred ----------
    sum4_k<<<(int)((TOT + 255) / 256), 256>>>(Sb, Sl, Sg, Sc, Ssum, TOT);
    gemm(Ssum, w1, b1, h1, BB * SEQ, DIM, DIM, DIM, DIM, DIM,
         0, 0, 0, 0, 0, 0, 1, 1, 1.f, true, true);
    gemm(h1, w2, b2, pr, BB * SEQ, DIM, DIM, DIM, DIM, DIM,
         0, 0, 0, 0, 0, 0, 1, 1, 1.f, true, false);
    add_ln_k<<<BB * SEQ, 256>>>(pr, Ssum, nullptr, ln2_g, ln2_b, Ff);
    pred_k<<<(BB * SEQ * 32 + 255) / 256, 256>>>(Ff, pred_w, pred_b, p_out);
}

// round 2
// speedup vs baseline: 4.0969x; 4.0969x over previous
#include <cuda_runtime.h>
#include <math.h>
#include <stdint.h>

#define BB 16
#define SEQ 512
#define DIM 512
#define NH 8
#define HD 64
#define LWIN 64
#define NQV 10000

// ---------------- scratch (device globals; no allocation allowed) ----------------
__device__ float g_M[BB*SEQ*DIM];
__device__ float g_E[BB*SEQ*DIM];
__device__ float g_qkv[BB*SEQ*3*DIM];
__device__ float g_scores[BB*NH*SEQ*SEQ];      // 134 MB
__device__ float g_ao[BB*SEQ*DIM];
__device__ float g_proj[BB*SEQ*DIM];
__device__ float g_Sbase[BB*SEQ*DIM];
__device__ float g_Slocal[BB*SEQ*DIM];
__device__ float g_Sglobal[BB*SEQ*DIM];
__device__ float g_Scross[BB*SEQ*DIM];
__device__ float g_qkv_loc[BB*LWIN*3*DIM];
__device__ float g_sc_loc[BB*NH*LWIN*LWIN];
__device__ float g_ao_loc[BB*LWIN*DIM];
__device__ float g_S[BB*SEQ*DIM];
__device__ float g_h1[BB*SEQ*DIM];
__device__ float g_F[BB*SEQ*DIM];

// ---------------- tf32 tensor-core batched GEMM ----------------
// C = scale*(A @ B[^T]) + bias, optional relu.
// Tile 128x128x32, 256 threads (8 warps, 2x4), warp tile 64x32.
// Operands staged in smem in m16n8k8 fragment order (conflict-free frag reads).

__device__ __forceinline__ uint32_t f2tf32(float f) {
    uint32_t u;
    asm("cvt.rna.tf32.f32 %0, %1;" : "=r"(u) : "f"(f));
    return u;
}

__device__ __forceinline__ void mma_tf32(float c[4], const uint32_t a[4], const uint32_t b[2]) {
    asm volatile(
        "mma.sync.aligned.m16n8k8.row.col.f32.tf32.tf32.f32 "
        "{%0,%1,%2,%3},{%4,%5,%6,%7},{%8,%9},{%0,%1,%2,%3};"
        : "+f"(c[0]), "+f"(c[1]), "+f"(c[2]), "+f"(c[3])
        : "r"(a[0]), "r"(a[1]), "r"(a[2]), "r"(a[3]), "r"(b[0]), "r"(b[1]));
}

// sA: 8 mtiles * 4 ksteps groups, each 32 lanes * 4 regs, group stride 132 words (pad)
// sB: 16 ntiles * 4 ksteps groups, each 32 lanes * 2 regs, group stride 66 words (pad)
#define AG_STRIDE 132
#define BG_STRIDE 66

__global__ __launch_bounds__(256, 2) void mma_gemm_k(
    const float* __restrict__ A, const float* __restrict__ B,
    const float* __restrict__ bias, float* __restrict__ C,
    int M, int N, int K, int lda, int ldb, int ldc,
    long sAb, long sAh, long sBb, long sBh, long sCb, long sCh,
    int hinner, float scale, int transB, int doRelu)
{
    __shared__ uint32_t sA[32 * AG_STRIDE];
    __shared__ uint32_t sB[64 * BG_STRIDE];

    int z  = blockIdx.z;
    int zb = z / hinner, zh = z % hinner;
    A += zb * sAb + zh * sAh;
    B += zb * sBb + zh * sBh;
    C += zb * sCb + zh * sCh;

    int m0 = blockIdx.y * 128, n0 = blockIdx.x * 128;
    int tid  = threadIdx.x;
    int lane = tid & 31, warp = tid >> 5;
    int wm = warp >> 2, wn = warp & 3;

    float c[4][4][4];
#pragma unroll
    for (int i = 0; i < 4; i++)
#pragma unroll
        for (int j = 0; j < 4; j++)
#pragma unroll
            for (int r = 0; r < 4; r++) c[i][j][r] = 0.f;

    for (int k0 = 0; k0 < K; k0 += 32) {
        // ---- stage A tile (128x32) into fragment-order smem ----
#pragma unroll
        for (int it = 0; it < 4; it++) {
            int idx = tid + it * 256;         // 0..1023 over 128m x 8 float4-k
            int m = idx >> 3, kq = idx & 7;
            float4 v = make_float4(0.f, 0.f, 0.f, 0.f);
            if (m0 + m < M)
                v = *reinterpret_cast<const float4*>(A + (long)(m0 + m) * lda + (k0 + kq * 4));
            int mi = m >> 4, r = m & 15;
            int rlow = r & 7, rhigh = r >> 3;
            float vv[4] = {v.x, v.y, v.z, v.w};
#pragma unroll
            for (int ci = 0; ci < 4; ci++) {
                int kk = kq * 4 + ci;
                int ki = kk >> 3, cc = kk & 7;
                int g = mi * 4 + ki;
                sA[g * AG_STRIDE + (rlow * 4 + (cc & 3)) * 4 + rhigh + 2 * (cc >> 2)] = f2tf32(vv[ci]);
            }
        }
        // ---- stage B tile (32k x 128n) ----
        if (transB) {
#pragma unroll
            for (int it = 0; it < 4; it++) {
                int idx = tid + it * 256;     // 128n x 8 float4-k
                int n = idx >> 3, kq = idx & 7;
                float4 v = make_float4(0.f, 0.f, 0.f, 0.f);
                if (n0 + n < N)
                    v = *reinterpret_cast<const float4*>(B + (long)(n0 + n) * ldb + (k0 + kq * 4));
                int ni = n >> 3, nl = n & 7;
                float vv[4] = {v.x, v.y, v.z, v.w};
#pragma unroll
                for (int ci = 0; ci < 4; ci++) {
                    int kk = kq * 4 + ci;
                    int ki = kk >> 3;
                    int g = ni * 4 + ki;
                    sB[g * BG_STRIDE + (nl * 4 + (kk & 3)) * 2 + ((kk & 7) >> 2)] = f2tf32(vv[ci]);
                }
            }
        } else {
#pragma unroll
            for (int it = 0; it < 4; it++) {
                int idx = tid + it * 256;     // 32k x 32 float4-n, k spread inside warp
                int k  = (idx & 3) | ((idx >> 7) << 2);
                int nq = (idx >> 2) & 31;
                int n  = nq * 4;
                float4 v = make_float4(0.f, 0.f, 0.f, 0.f);
                if (n0 + n < N)
                    v = *reinterpret_cast<const float4*>(B + (long)(k0 + k) * ldb + (n0 + n));
                int ki = k >> 3;
                float vv[4] = {v.x, v.y, v.z, v.w};
#pragma unroll
                for (int ci = 0; ci < 4; ci++) {
                    int nn = n + ci;
                    int g = (nn >> 3) * 4 + ki;
                    sB[g * BG_STRIDE + ((nn & 7) * 4 + (k & 3)) * 2 + ((k & 7) >> 2)] = f2tf32(vv[ci]);
                }
            }
        }
        __syncthreads();

        // ---- compute: 4 ksteps x (4 mtiles x 4 ntiles) mma ----
#pragma unroll
        for (int ki = 0; ki < 4; ki++) {
            uint32_t af[4][4];
            uint32_t bf[4][2];
#pragma unroll
            for (int i = 0; i < 4; i++)
                *reinterpret_cast<uint4*>(af[i]) =
                    *reinterpret_cast<const uint4*>(&sA[(((wm * 4 + i) * 4 + ki)) * AG_STRIDE + lane * 4]);
#pragma unroll
            for (int j = 0; j < 4; j++)
                *reinterpret_cast<uint2*>(bf[j]) =
                    *reinterpret_cast<const uint2*>(&sB[(((wn * 4 + j) * 4 + ki)) * BG_STRIDE + lane * 2]);
#pragma unroll
            for (int i = 0; i < 4; i++)
#pragma unroll
                for (int j = 0; j < 4; j++)
                    mma_tf32(c[i][j], af[i], bf[j]);
        }
        __syncthreads();
    }

    // ---- epilogue ----
    int gid = lane >> 2, tig = lane & 3;
#pragma unroll
    for (int i = 0; i < 4; i++) {
        int row0 = m0 + wm * 64 + i * 16 + gid;
#pragma unroll
        for (int j = 0; j < 4; j++) {
            int col = n0 + wn * 32 + j * 8 + tig * 2;
            if (col >= N) continue;
            float b0 = bias ? bias[col] : 0.f;
            float b1 = bias ? bias[col + 1] : 0.f;
            if (row0 < M) {
                float v0 = c[i][j][0] * scale + b0;
                float v1 = c[i][j][1] * scale + b1;
                if (doRelu) { v0 = fmaxf(v0, 0.f); v1 = fmaxf(v1, 0.f); }
                *reinterpret_cast<float2*>(&C[(long)row0 * ldc + col]) = make_float2(v0, v1);
            }
            if (row0 + 8 < M) {
                float v0 = c[i][j][2] * scale + b0;
                float v1 = c[i][j][3] * scale + b1;
                if (doRelu) { v0 = fmaxf(v0, 0.f); v1 = fmaxf(v1, 0.f); }
                *reinterpret_cast<float2*>(&C[(long)(row0 + 8) * ldc + col]) = make_float2(v0, v1);
            }
        }
    }
}

// ---------------- embedding gather ----------------
__global__ void embed_k(const int* __restrict__ q, const int* __restrict__ r,
                        const int* __restrict__ qry,
                        const float* __restrict__ Memb, const float* __restrict__ Eemb,
                        const float* __restrict__ P)
{
    long idx = (long)blockIdx.x * blockDim.x + threadIdx.x;
    long total = (long)BB * SEQ * DIM;
    if (idx >= total) return;
    int d = (int)(idx % DIM);
    long bn = idx / DIM;
    int n = (int)(bn % SEQ);
    int x = q[bn] + NQV * r[bn];
    g_M[idx] = Memb[(long)x * DIM + d] + P[n * DIM + d];
    g_E[idx] = Eemb[(long)qry[bn] * DIM + d];
}

// ---------------- block reductions ----------------
__device__ __forceinline__ float blk_reduce(float v, bool is_max, float ident) {
    __shared__ float red[32];
    __shared__ float bc;
    int t = threadIdx.x;
    int nw = blockDim.x >> 5;
#pragma unroll
    for (int o = 16; o; o >>= 1) {
        float other = __shfl_xor_sync(0xffffffffu, v, o);
        v = is_max ? fmaxf(v, other) : (v + other);
    }
    if ((t & 31) == 0) red[t >> 5] = v;
    __syncthreads();
    if (t < 32) {
        float s = (t < nw) ? red[t] : ident;
#pragma unroll
        for (int o = 16; o; o >>= 1) {
            float other = __shfl_xor_sync(0xffffffffu, s, o);
            s = is_max ? fmaxf(s, other) : (s + other);
        }
        if (t == 0) bc = s;
    }
    __syncthreads();
    float ret = bc;
    __syncthreads();
    return ret;
}

// ---------------- softmax over rows (causal => only first i+1 cols valid, tail zeroed) ----------------
__global__ void softmax_k(float* __restrict__ S, int rows_per, int cols, int causal)
{
    long row = blockIdx.x;
    int i = (int)(row % rows_per);
    float* p = S + row * (long)cols;
    int lim = causal ? (i + 1) : cols;
    int t = threadIdx.x;

    float mx = -1e30f;
    for (int j = t; j < lim; j += blockDim.x) mx = fmaxf(mx, p[j]);
    float gmax = blk_reduce(mx, true, -1e30f);

    float s = 0.f;
    for (int j = t; j < lim; j += blockDim.x) { float e = expf(p[j] - gmax); p[j] = e; s += e; }
    float gsum = blk_reduce(s, false, 0.f);

    float inv = 1.f / gsum;
    for (int j = t; j < lim; j += blockDim.x) p[j] *= inv;
    for (int j = lim + t; j < cols; j += blockDim.x) p[j] = 0.f;
}

// ---------------- head-mean of base attention into output ----------------
__global__ void attn_mean_k(const float* __restrict__ S, float* __restrict__ out)
{
    long idx = (long)blockIdx.x * blockDim.x + threadIdx.x;
    long total = (long)BB * SEQ * SEQ;
    if (idx >= total) return;
    long b = idx / ((long)SEQ * SEQ);
    long rem = idx % ((long)SEQ * SEQ);
    float s = 0.f;
#pragma unroll
    for (int h = 0; h < NH; h++)
        s += S[((long)(b * NH + h)) * SEQ * SEQ + rem];
    out[idx] = s * (1.f / NH);
}

// ---------------- fused residual add + LayerNorm (c may be null) ----------------
__global__ __launch_bounds__(256) void add_ln_k(
    const float* __restrict__ a, const float* __restrict__ b, const float* __restrict__ c,
    const float* __restrict__ gam, const float* __restrict__ bet, float* __restrict__ out)
{
    long row = blockIdx.x;
    int t = threadIdx.x;
    long base = row * (long)DIM;
    float x0 = a[base + t] + b[base + t] + (c ? c[base + t] : 0.f);
    float x1 = a[base + t + 256] + b[base + t + 256] + (c ? c[base + t + 256] : 0.f);
    float mean = blk_reduce(x0 + x1, false, 0.f) * (1.f / DIM);
    float d0 = x0 - mean, d1 = x1 - mean;
    float var = blk_reduce(d0 * d0 + d1 * d1, false, 0.f) * (1.f / DIM);
    float inv = rsqrtf(var + 1e-5f);
    out[base + t]       = d0 * inv * gam[t]       + bet[t];
    out[base + t + 256] = d1 * inv * gam[t + 256] + bet[t + 256];
}

// ---------------- misc elementwise ----------------
__global__ void zero_k(float* __restrict__ p, long n)
{
    long idx = (long)blockIdx.x * blockDim.x + threadIdx.x;
    if (idx < n) p[idx] = 0.f;
}

__global__ void sum4_k(const float* __restrict__ a, const float* __restrict__ b,
                       const float* __restrict__ c, const float* __restrict__ d,
                       float* __restrict__ out, long n)
{
    long idx = (long)blockIdx.x * blockDim.x + threadIdx.x;
    if (idx < n) out[idx] = a[idx] + b[idx] + c[idx] + d[idx];
}

// ---------------- prediction head: sigmoid(F @ w^T + b) ----------------
__global__ void pred_k(const float* __restrict__ F, const float* __restrict__ w,
                       const float* __restrict__ bias, float* __restrict__ out)
{
    int gw = (blockIdx.x * blockDim.x + threadIdx.x) >> 5;
    int lane = threadIdx.x & 31;
    if (gw >= BB * SEQ) return;
    const float* f = F + (long)gw * DIM;
    float s = 0.f;
    for (int j = lane; j < DIM; j += 32) s += f[j] * w[j];
#pragma unroll
    for (int o = 16; o; o >>= 1) s += __shfl_xor_sync(0xffffffffu, s, o);
    if (lane == 0) out[gw] = 1.f / (1.f + expf(-(s + bias[0])));
}

// ---------------- host side ----------------
static float* sym_addr(const void* symbol) {
    void* p = nullptr;
    cudaGetSymbolAddress(&p, symbol);
    return (float*)p;
}

static void gemm(const float* A, const float* B, const float* bias, float* C,
                 int M, int N, int K, int lda, int ldb, int ldc,
                 long sAb, long sAh, long sBb, long sBh, long sCb, long sCh,
                 int batch, int hinner, float scale, bool transB, bool relu)
{
    dim3 grid((N + 127) / 128, (M + 127) / 128, batch);
    mma_gemm_k<<<grid, 256>>>(A, B, bias, C, M, N, K, lda, ldb, ldc,
                              sAb, sAh, sBb, sBh, sCb, sCh, hinner, scale,
                              transB ? 1 : 0, relu ? 1 : 0);
}

extern "C" void kernel_launch(void* const* d_in, const int* in_sizes, int n_in,
                              void* d_out, int out_size)
{
    const int*   q_i    = (const int*)d_in[0];
    const int*   r_i    = (const int*)d_in[1];
    const int*   qry_i  = (const int*)d_in[2];
    const float* Memb   = (const float*)d_in[3];
    const float* Eemb   = (const float*)d_in[4];
    const float* P      = (const float*)d_in[5];
    const float* base_iw = (const float*)d_in[6];
    const float* base_ib = (const float*)d_in[7];
    const float* base_ow = (const float*)d_in[8];
    const float* base_ob = (const float*)d_in[9];
    const float* loc_iw  = (const float*)d_in[10];
    const float* loc_ib  = (const float*)d_in[11];
    const float* loc_ow  = (const float*)d_in[12];
    const float* loc_ob  = (const float*)d_in[13];
    const float* glob_iw = (const float*)d_in[14];
    const float* glob_ib = (const float*)d_in[15];
    const float* glob_ow = (const float*)d_in[16];
    const float* glob_ob = (const float*)d_in[17];
    const float* cross_iw = (const float*)d_in[18];
    const float* cross_ib = (const float*)d_in[19];
    const float* cross_ow = (const float*)d_in[20];
    const float* cross_ob = (const float*)d_in[21];
    const float* ln1_g = (const float*)d_in[22];
    const float* ln1_b = (const float*)d_in[23];
    const float* w1 = (const float*)d_in[24];
    const float* b1 = (const float*)d_in[25];
    const float* w2 = (const float*)d_in[26];
    const float* b2 = (const float*)d_in[27];
    const float* ln2_g = (const float*)d_in[28];
    const float* ln2_b = (const float*)d_in[29];
    const float* pred_w = (const float*)d_in[30];
    const float* pred_b = (const float*)d_in[31];

    float* out   = (float*)d_out;
    float* p_out = out;                 // [B, N]
    float* a_out = out + BB * SEQ;      // [B, N, N]

    float* M_  = sym_addr(g_M);
    float* E_  = sym_addr(g_E);
    float* qkv = sym_addr(g_qkv);
    float* sc  = sym_addr(g_scores);
    float* ao  = sym_addr(g_ao);
    float* pr  = sym_addr(g_proj);
    float* Sb  = sym_addr(g_Sbase);
    float* Sl  = sym_addr(g_Slocal);
    float* Sg  = sym_addr(g_Sglobal);
    float* Sc  = sym_addr(g_Scross);
    float* qkvL = sym_addr(g_qkv_loc);
    float* scL  = sym_addr(g_sc_loc);
    float* aoL  = sym_addr(g_ao_loc);
    float* Ssum = sym_addr(g_S);
    float* h1   = sym_addr(g_h1);
    float* Ff   = sym_addr(g_F);

    const long TOT = (long)BB * SEQ * DIM;
    const int  BN3 = 3 * DIM;
    const float SCL = 0.125f;           // 1/sqrt(64)
    const int BH = BB * NH;

    // 1. embeddings
    embed_k<<<(int)((TOT + 255) / 256), 256>>>(q_i, r_i, qry_i, Memb, Eemb, P);

    // ---------- base MHA: Q from E, K/V from M, causal ----------
    gemm(E_, base_iw, base_ib, qkv, BB * SEQ, DIM, DIM, DIM, DIM, BN3,
         0, 0, 0, 0, 0, 0, 1, 1, 1.f, true, false);
    gemm(M_, base_iw + DIM * DIM, base_ib + DIM, qkv + DIM, BB * SEQ, 2 * DIM, DIM, DIM, DIM, BN3,
         0, 0, 0, 0, 0, 0, 1, 1, 1.f, true, false);
    gemm(qkv, qkv + DIM, nullptr, sc, SEQ, SEQ, HD, BN3, BN3, SEQ,
         (long)SEQ * BN3, HD, (long)SEQ * BN3, HD, (long)NH * SEQ * SEQ, (long)SEQ * SEQ,
         BH, NH, SCL, true, false);
    softmax_k<<<BH * SEQ, 128>>>(sc, SEQ, SEQ, 1);
    attn_mean_k<<<(int)(((long)BB * SEQ * SEQ + 255) / 256), 256>>>(sc, a_out);
    gemm(sc, qkv + 2 * DIM, nullptr, ao, SEQ, HD, SEQ, SEQ, BN3, DIM,
         (long)NH * SEQ * SEQ, (long)SEQ * SEQ, (long)SEQ * BN3, HD, (long)SEQ * DIM, HD,
         BH, NH, 1.f, false, false);
    gemm(ao, base_ow, base_ob, pr, BB * SEQ, DIM, DIM, DIM, DIM, DIM,
         0, 0, 0, 0, 0, 0, 1, 1, 1.f, true, false);
    add_ln_k<<<BB * SEQ, 256>>>(pr, M_, E_, ln1_g, ln1_b, Sb);

    // ---------- local MHA on last LW rows of S_base ----------
    gemm(Sb + (SEQ - LWIN) * DIM, loc_iw, loc_ib, qkvL, LWIN, BN3, DIM, DIM, DIM, BN3,
         (long)SEQ * DIM, 0, 0, 0, (long)LWIN * BN3, 0, BB, 1, 1.f, true, false);
    gemm(qkvL, qkvL + DIM, nullptr, scL, LWIN, LWIN, HD, BN3, BN3, LWIN,
         (long)LWIN * BN3, HD, (long)LWIN * BN3, HD, (long)NH * LWIN * LWIN, (long)LWIN * LWIN,
         BH, NH, SCL, true, false);
    softmax_k<<<BH * LWIN, 128>>>(scL, LWIN, LWIN, 1);
    gemm(scL, qkvL + 2 * DIM, nullptr, aoL, LWIN, HD, LWIN, LWIN, BN3, DIM,
         (long)NH * LWIN * LWIN, (long)LWIN * LWIN, (long)LWIN * BN3, HD, (long)LWIN * DIM, HD,
         BH, NH, 1.f, false, false);
    zero_k<<<(int)((TOT + 255) / 256), 256>>>(Sl, TOT);
    gemm(aoL, loc_ow, loc_ob, Sl + (SEQ - LWIN) * DIM, LWIN, DIM, DIM, DIM, DIM, DIM,
         (long)LWIN * DIM, 0, 0, 0, (long)SEQ * DIM, 0, BB, 1, 1.f, true, false);

    // ---------- global MHA: all from S_base, causal ----------
    gemm(Sb, glob_iw, glob_ib, qkv, BB * SEQ, BN3, DIM, DIM, DIM, BN3,
         0, 0, 0, 0, 0, 0, 1, 1, 1.f, true, false);
    gemm(qkv, qkv + DIM, nullptr, sc, SEQ, SEQ, HD, BN3, BN3, SEQ,
         (long)SEQ * BN3, HD, (long)SEQ * BN3, HD, (long)NH * SEQ * SEQ, (long)SEQ * SEQ,
         BH, NH, SCL, true, false);
    softmax_k<<<BH * SEQ, 128>>>(sc, SEQ, SEQ, 1);
    gemm(sc, qkv + 2 * DIM, nullptr, ao, SEQ, HD, SEQ, SEQ, BN3, DIM,
         (long)NH * SEQ * SEQ, (long)SEQ * SEQ, (long)SEQ * BN3, HD, (long)SEQ * DIM, HD,
         BH, NH, 1.f, false, false);
    gemm(ao, glob_ow, glob_ob, Sg, BB * SEQ, DIM, DIM, DIM, DIM, DIM,
         0, 0, 0, 0, 0, 0, 1, 1, 1.f, true, false);

    // ---------- cross MHA: Q from S_base, K/V from S_local, no mask ----------
    gemm(Sb, cross_iw, cross_ib, qkv, BB * SEQ, DIM, DIM, DIM, DIM, BN3,
         0, 0, 0, 0, 0, 0, 1, 1, 1.f, true, false);
    gemm(Sl, cross_iw + DIM * DIM, cross_ib + DIM, qkv + DIM, BB * SEQ, 2 * DIM, DIM, DIM, DIM, BN3,
         0, 0, 0, 0, 0, 0, 1, 1, 1.f, true, false);
    gemm(qkv, qkv + DIM, nullptr, sc, SEQ, SEQ, HD, BN3, BN3, SEQ,
         (long)SEQ * BN3, HD, (long)SEQ * BN3, HD, (long)NH * SEQ * SEQ, (long)SEQ * SEQ,
         BH, NH, SCL, true, false);
    softmax_k<<<BH * SEQ, 128>>>(sc, SEQ, SEQ, 0);
    gemm(sc, qkv + 2 * DIM, nullptr, ao, SEQ, HD, SEQ, SEQ, BN3, DIM,
         (long)NH * SEQ * SEQ, (long)SEQ * SEQ, (long)SEQ * BN3, HD, (long)SEQ * DIM, HD,
         BH, NH, 1.f, false, false);
    gemm(ao, cross_ow, cross_ob, Sc, BB * SEQ, DIM, DIM, DIM, DIM, DIM,
         0, 0, 0, 0, 0, 0, 1, 1, 1.f, true, false);

    // ---------- combine + FFN + LN + pred ----------
    sum4_k<<<(int)((TOT + 255) / 256), 256>>>(Sb, Sl, Sg, Sc, Ssum, TOT);
    gemm(Ssum, w1, b1, h1, BB * SEQ, DIM, DIM, DIM, DIM, DIM,
         0, 0, 0, 0, 0, 0, 1, 1, 1.f, true, true);
    gemm(h1, w2, b2, pr, BB * SEQ, DIM, DIM, DIM, DIM, DIM,
         0, 0, 0, 0, 0, 0, 1, 1, 1.f, true, false);
    add_ln_k<<<BB * SEQ, 256>>>(pr, Ssum, nullptr, ln2_g, ln2_b, Ff);
    pred_k<<<(BB * SEQ * 32 + 255) / 256, 256>>>(Ff, pred_w, pred_b, p_out);
}